// round 2
// baseline (speedup 1.0000x reference)
#include <cuda_runtime.h>

#define HASH_SIZE 10240
#define PROJ_DIM  128
#define MODEL_DIM 512
#define NBATCH    8
#define SEQ       8192

// Fused table: fused[h][m] = scale * sum_k embed[h][k] * proj[m][k]
// 10240 * 512 * 4B = 21 MB — static device scratch (allocation-free rule).
__device__ float g_fused[HASH_SIZE * MODEL_DIM];

// ---------------------------------------------------------------------------
// Kernel 1: build the fused table. C = scale * E (10240x128) @ P^T (128x512).
// Both operands are K-major (row-major [rows, 128]) -> NT GEMM.
// Tile: BM=128, BN=128, BK=32, 256 threads, 8x8 register micro-tile,
// strided thread mapping (m = ty + 16*i, n = tx + 16*j) for conflict-free LDS.
// ---------------------------------------------------------------------------
#define BM 128
#define BN 128
#define BK 32

__global__ __launch_bounds__(256) void build_table_kernel(
    const float* __restrict__ E,
    const float* __restrict__ P,
    const float* __restrict__ scale_p)
{
    __shared__ float As[BK][BM];   // transposed: [k][m]
    __shared__ float Bs[BK][BN];   // transposed: [k][n]

    const int tid = threadIdx.x;
    const int tx  = tid & 15;      // n micro-index
    const int ty  = tid >> 4;      // m micro-index
    const int m0  = blockIdx.x * BM;
    const int n0  = blockIdx.y * BN;

    float acc[8][8];
    #pragma unroll
    for (int i = 0; i < 8; i++)
        #pragma unroll
        for (int j = 0; j < 8; j++) acc[i][j] = 0.0f;

    const int lrow = tid >> 3;         // 0..31
    const int lcol = (tid & 7) << 2;   // 0,4,...,28

    for (int k0 = 0; k0 < PROJ_DIM; k0 += BK) {
        // Load BMxBK of E and BNxBK of P, transposed into shared.
        // Global reads: float4 along K (coalesced: 8 threads cover one 128B row-chunk).
        #pragma unroll
        for (int r = 0; r < 4; r++) {
            const int m = lrow + r * 32;
            float4 va = *(const float4*)&E[(size_t)(m0 + m) * PROJ_DIM + k0 + lcol];
            As[lcol + 0][m] = va.x;
            As[lcol + 1][m] = va.y;
            As[lcol + 2][m] = va.z;
            As[lcol + 3][m] = va.w;
            float4 vb = *(const float4*)&P[(size_t)(n0 + m) * PROJ_DIM + k0 + lcol];
            Bs[lcol + 0][m] = vb.x;
            Bs[lcol + 1][m] = vb.y;
            Bs[lcol + 2][m] = vb.z;
            Bs[lcol + 3][m] = vb.w;
        }
        __syncthreads();

        #pragma unroll
        for (int k = 0; k < BK; k++) {
            float a[8], b[8];
            #pragma unroll
            for (int i = 0; i < 8; i++) a[i] = As[k][ty + i * 16];
            #pragma unroll
            for (int j = 0; j < 8; j++) b[j] = Bs[k][tx + j * 16];
            #pragma unroll
            for (int i = 0; i < 8; i++)
                #pragma unroll
                for (int j = 0; j < 8; j++)
                    acc[i][j] = fmaf(a[i], b[j], acc[i][j]);
        }
        __syncthreads();
    }

    const float s = *scale_p;
    #pragma unroll
    for (int i = 0; i < 8; i++) {
        const int m = m0 + ty + i * 16;
        float* dst = &g_fused[(size_t)m * MODEL_DIM + n0];
        #pragma unroll
        for (int j = 0; j < 8; j++)
            dst[tx + j * 16] = acc[i][j] * s;
    }
}

// ---------------------------------------------------------------------------
// Kernel 2: hash + gather + stream out.
// One block (128 threads) per token; each thread moves one float4 (512 floats
// per token). Table reads hit L2 (21 MB table, avg 6.4x reuse); output is a
// pure coalesced 134 MB stream.
// ---------------------------------------------------------------------------
__global__ __launch_bounds__(128) void gather_kernel(
    const int* __restrict__ tok,
    float* __restrict__ out)
{
    const int token = blockIdx.x;          // 0 .. B*S-1
    const int s = token & (SEQ - 1);

    int h;
    if (s == 0) {
        h = HASH_SIZE - 1;
    } else {
        // Same-address LDG across the block -> broadcast, 1 transaction each.
        const int t1 = tok[token];
        const int t0 = tok[token - 1];
        // 36313*50256 and 27191*50256 both < 2^31: no wrap, matches jnp exactly.
        h = ((36313 * t1) ^ (27191 * t0)) % (HASH_SIZE - 1);
    }

    const float4* src = (const float4*)&g_fused[(size_t)h * MODEL_DIM];
    float4* dst       = (float4*)&out[(size_t)token * MODEL_DIM];
    dst[threadIdx.x] = src[threadIdx.x];
}

// ---------------------------------------------------------------------------
// Launch: table build then gather, same stream (ordered), graph-capturable.
// Inputs per metadata order: token_ids(i32), embed_weight(f32), proj_weight(f32), scale(f32[1])
// ---------------------------------------------------------------------------
extern "C" void kernel_launch(void* const* d_in, const int* in_sizes, int n_in,
                              void* d_out, int out_size)
{
    const int*   tok   = (const int*)d_in[0];
    const float* E     = (const float*)d_in[1];
    const float* P     = (const float*)d_in[2];
    const float* scale = (const float*)d_in[3];
    float*       out   = (float*)d_out;

    dim3 gemm_grid(HASH_SIZE / BM, MODEL_DIM / BN);   // (80, 4)
    build_table_kernel<<<gemm_grid, 256>>>(E, P, scale);

    gather_kernel<<<NBATCH * SEQ, 128>>>(tok, out);
}

// round 3
// speedup vs baseline: 1.4356x; 1.4356x over previous
#include <cuda_runtime.h>

#define HASH_SIZE 10240
#define PROJ_DIM  128
#define MODEL_DIM 512
#define NBATCH    8
#define SEQ       8192

// Fused table: fused[h][m] = scale * sum_k embed[h][k] * proj[m][k]  (21 MB)
__device__ float g_fused[HASH_SIZE * MODEL_DIM];

// ---------------------------------------------------------------------------
// Kernel 1: build the fused table. C = scale * E (10240x128) @ P^T (512x128)^T
// Tile BM=128, BN=64, BK=32, 256 threads, 8x4 micro-tile, k-vectorized (4 k
// per step via float4), quad-XOR smem swizzle for conflict-free LDS/STS.
// 3 blocks/SM; grid 80x8 = 640 blocks.
// ---------------------------------------------------------------------------
#define GBM 128
#define GBN 64
#define GBK 32   // 8 float4 quads per row

// physical float index of logical quad q in row r (XOR swizzle on quad)
__device__ __forceinline__ int sw_idx(int row, int q) {
    return row * GBK + ((q ^ ((row >> 2) & 7)) << 2);
}

__global__ __launch_bounds__(256, 3) void build_table_kernel(
    const float* __restrict__ E,
    const float* __restrict__ P,
    const float* __restrict__ scale_p)
{
    __shared__ float As[GBM * GBK];   // [m][k-quad swizzled]
    __shared__ float Bs[GBN * GBK];   // [n][k-quad swizzled]

    const int tid = threadIdx.x;
    const int mt  = tid & 15;         // m micro: rows mt*4..+3 and +64..
    const int nt  = tid >> 4;         // n micro: cols nt*4..+3
    const int m0  = blockIdx.x * GBM;
    const int n0  = blockIdx.y * GBN;

    const int lrow = tid >> 3;        // 0..31  (tile-load row within pass)
    const int lkq  = tid & 7;         // 0..7   (k-quad)

    float acc[8][4];
    #pragma unroll
    for (int i = 0; i < 8; i++)
        #pragma unroll
        for (int j = 0; j < 4; j++) acc[i][j] = 0.0f;

    const int msw = mt & 7;           // load-side swizzle for a-frags
    const int nsw = nt & 7;           // for b-frags

    for (int k0 = 0; k0 < PROJ_DIM; k0 += GBK) {
        // ---- load A tile: 128 rows x 8 quads, 4 passes of 32 rows
        #pragma unroll
        for (int r = 0; r < 4; r++) {
            const int row = lrow + r * 32;
            float4 v = *(const float4*)&E[(size_t)(m0 + row) * PROJ_DIM + k0 + lkq * 4];
            *(float4*)&As[sw_idx(row, lkq)] = v;
        }
        // ---- load B tile: 64 rows x 8 quads, 2 passes
        #pragma unroll
        for (int r = 0; r < 2; r++) {
            const int row = lrow + r * 32;
            float4 v = *(const float4*)&P[(size_t)(n0 + row) * PROJ_DIM + k0 + lkq * 4];
            *(float4*)&Bs[sw_idx(row, lkq)] = v;
        }
        __syncthreads();

        // ---- compute: 8 k-quad steps, 4 k per step
        #pragma unroll
        for (int kq = 0; kq < GBK / 4; kq++) {
            float4 b[4];
            #pragma unroll
            for (int j = 0; j < 4; j++)
                b[j] = *(const float4*)&Bs[(nt * 4 + j) * GBK + ((kq ^ nsw) << 2)];

            float4 a[8];
            #pragma unroll
            for (int i = 0; i < 4; i++) {
                a[i]     = *(const float4*)&As[(mt * 4 + i)      * GBK + ((kq ^ msw) << 2)];
                a[i + 4] = *(const float4*)&As[(64 + mt * 4 + i) * GBK + ((kq ^ msw) << 2)];
            }
            #pragma unroll
            for (int i = 0; i < 8; i++)
                #pragma unroll
                for (int j = 0; j < 4; j++) {
                    acc[i][j] = fmaf(a[i].x, b[j].x, acc[i][j]);
                    acc[i][j] = fmaf(a[i].y, b[j].y, acc[i][j]);
                    acc[i][j] = fmaf(a[i].z, b[j].z, acc[i][j]);
                    acc[i][j] = fmaf(a[i].w, b[j].w, acc[i][j]);
                }
        }
        __syncthreads();
    }

    const float s = *scale_p;
    #pragma unroll
    for (int i = 0; i < 8; i++) {
        const int m = m0 + ((i < 4) ? (mt * 4 + i) : (64 + mt * 4 + i - 4));
        float4 v = make_float4(acc[i][0] * s, acc[i][1] * s,
                               acc[i][2] * s, acc[i][3] * s);
        *(float4*)&g_fused[(size_t)m * MODEL_DIM + n0 + nt * 4] = v;
    }
}

// ---------------------------------------------------------------------------
// Kernel 2: hash + gather + stream out. Warp per token: each lane moves
// 4 independent float4 (MLP=4). Output stored with .cs (evict-first) so the
// 134 MB stream doesn't evict the 21 MB table from L2.
// ---------------------------------------------------------------------------
__global__ __launch_bounds__(256) void gather_kernel(
    const int* __restrict__ tok,
    float* __restrict__ out)
{
    const int warp  = (blockIdx.x * 256 + threadIdx.x) >> 5;   // token id
    const int lane  = threadIdx.x & 31;
    const int s     = warp & (SEQ - 1);

    int h;
    if (s == 0) {
        h = HASH_SIZE - 1;
    } else {
        const int t1 = __ldg(tok + warp);
        const int t0 = __ldg(tok + warp - 1);
        // products < 2^31: no wrap; matches jnp.mod exactly
        h = ((36313 * t1) ^ (27191 * t0)) % (HASH_SIZE - 1);
    }

    const float4* src = (const float4*)(g_fused + (size_t)h * MODEL_DIM);
    float4*       dst = (float4*)(out + (size_t)warp * MODEL_DIM);

    float4 v0 = __ldg(src + lane);
    float4 v1 = __ldg(src + lane + 32);
    float4 v2 = __ldg(src + lane + 64);
    float4 v3 = __ldg(src + lane + 96);
    __stcs(dst + lane,      v0);
    __stcs(dst + lane + 32, v1);
    __stcs(dst + lane + 64, v2);
    __stcs(dst + lane + 96, v3);
}

// ---------------------------------------------------------------------------
// Inputs (metadata order): token_ids(i32), embed_weight(f32), proj_weight(f32), scale(f32[1])
// ---------------------------------------------------------------------------
extern "C" void kernel_launch(void* const* d_in, const int* in_sizes, int n_in,
                              void* d_out, int out_size)
{
    const int*   tok   = (const int*)d_in[0];
    const float* E     = (const float*)d_in[1];
    const float* P     = (const float*)d_in[2];
    const float* scale = (const float*)d_in[3];
    float*       out   = (float*)d_out;

    dim3 gemm_grid(HASH_SIZE / GBM, MODEL_DIM / GBN);   // (80, 8)
    build_table_kernel<<<gemm_grid, 256>>>(E, P, scale);

    gather_kernel<<<(NBATCH * SEQ) / 8, 256>>>(tok, out);
}

// round 4
// speedup vs baseline: 1.5484x; 1.0785x over previous
#include <cuda_runtime.h>

#define HASH_SIZE 10240
#define PROJ_DIM  128
#define MODEL_DIM 512
#define NBATCH    8
#define SEQ       8192

// Fused table: fused[h][m] = scale * sum_k embed[h][k] * proj[m][k]  (21 MB)
__device__ float g_fused[HASH_SIZE * MODEL_DIM];

// ---------------------------------------------------------------------------
// Kernel 1: build the fused table. C = scale * E (10240x128) @ P (512x128)^T
// Tile BM=128, BN=64, BK=32, 256 threads, 8x4 micro-tile, k-vectorized
// (4 k per step via float4), quad-XOR smem swizzle (conflict-free LDS/STS).
// NO min-blocks clause: ptxas gets ~90-100 regs -> no spill (R3's 84-reg cap
// under (256,3) spilled the inner loop -> 2.5x slowdown).
// ---------------------------------------------------------------------------
#define GBM 128
#define GBN 64
#define GBK 32   // 8 float4 quads per row

__device__ __forceinline__ int sw_idx(int row, int q) {
    return row * GBK + ((q ^ ((row >> 2) & 7)) << 2);
}

__global__ __launch_bounds__(256) void build_table_kernel(
    const float* __restrict__ E,
    const float* __restrict__ P,
    const float* __restrict__ scale_p)
{
    __shared__ float As[GBM * GBK];   // [m][k-quad swizzled]
    __shared__ float Bs[GBN * GBK];   // [n][k-quad swizzled]

    const int tid = threadIdx.x;
    const int mt  = tid & 15;         // m micro: rows mt*4..+3 and +64..
    const int nt  = tid >> 4;         // n micro: cols nt*4..+3
    const int m0  = blockIdx.x * GBM;
    const int n0  = blockIdx.y * GBN;

    const int lrow = tid >> 3;        // 0..31  (tile-load row within pass)
    const int lkq  = tid & 7;         // 0..7   (k-quad)

    float acc[8][4];
    #pragma unroll
    for (int i = 0; i < 8; i++)
        #pragma unroll
        for (int j = 0; j < 4; j++) acc[i][j] = 0.0f;

    const int msw = mt & 7;           // load-side swizzle for a-frags
    const int nsw = nt & 7;           // for b-frags

    for (int k0 = 0; k0 < PROJ_DIM; k0 += GBK) {
        #pragma unroll
        for (int r = 0; r < 4; r++) {
            const int row = lrow + r * 32;
            float4 v = *(const float4*)&E[(size_t)(m0 + row) * PROJ_DIM + k0 + lkq * 4];
            *(float4*)&As[sw_idx(row, lkq)] = v;
        }
        #pragma unroll
        for (int r = 0; r < 2; r++) {
            const int row = lrow + r * 32;
            float4 v = *(const float4*)&P[(size_t)(n0 + row) * PROJ_DIM + k0 + lkq * 4];
            *(float4*)&Bs[sw_idx(row, lkq)] = v;
        }
        __syncthreads();

        #pragma unroll
        for (int kq = 0; kq < GBK / 4; kq++) {
            float4 b[4];
            #pragma unroll
            for (int j = 0; j < 4; j++)
                b[j] = *(const float4*)&Bs[(nt * 4 + j) * GBK + ((kq ^ nsw) << 2)];

            float4 a[8];
            #pragma unroll
            for (int i = 0; i < 4; i++) {
                a[i]     = *(const float4*)&As[(mt * 4 + i)      * GBK + ((kq ^ msw) << 2)];
                a[i + 4] = *(const float4*)&As[(64 + mt * 4 + i) * GBK + ((kq ^ msw) << 2)];
            }
            #pragma unroll
            for (int i = 0; i < 8; i++)
                #pragma unroll
                for (int j = 0; j < 4; j++) {
                    acc[i][j] = fmaf(a[i].x, b[j].x, acc[i][j]);
                    acc[i][j] = fmaf(a[i].y, b[j].y, acc[i][j]);
                    acc[i][j] = fmaf(a[i].z, b[j].z, acc[i][j]);
                    acc[i][j] = fmaf(a[i].w, b[j].w, acc[i][j]);
                }
        }
        __syncthreads();
    }

    const float s = *scale_p;
    #pragma unroll
    for (int i = 0; i < 8; i++) {
        const int m = m0 + ((i < 4) ? (mt * 4 + i) : (64 + mt * 4 + i - 4));
        float4 v = make_float4(acc[i][0] * s, acc[i][1] * s,
                               acc[i][2] * s, acc[i][3] * s);
        *(float4*)&g_fused[(size_t)m * MODEL_DIM + n0 + nt * 4] = v;
    }
}

// ---------------------------------------------------------------------------
// Kernel 2: hash + gather + stream out. Each warp handles TWO tokens so every
// lane has 8 independent LDGs in flight (MLP=8) before any store. Output via
// .cs (evict-first) so the 134 MB stream doesn't evict the 21 MB table.
// ---------------------------------------------------------------------------
__device__ __forceinline__ int hash_at(const int* __restrict__ tok, int t) {
    const int s = t & (SEQ - 1);
    if (s == 0) return HASH_SIZE - 1;
    const int t1 = __ldg(tok + t);
    const int t0 = __ldg(tok + t - 1);
    // products < 2^31: no wrap; matches jnp.mod exactly
    return ((36313 * t1) ^ (27191 * t0)) % (HASH_SIZE - 1);
}

__global__ __launch_bounds__(256) void gather_kernel(
    const int* __restrict__ tok,
    float* __restrict__ out)
{
    const int warp = (blockIdx.x * 256 + threadIdx.x) >> 5;  // 0..8191
    const int lane = threadIdx.x & 31;
    const int tA   = warp * 2;
    const int tB   = warp * 2 + 1;

    const int hA = hash_at(tok, tA);
    const int hB = hash_at(tok, tB);

    const float4* sA = (const float4*)(g_fused + (size_t)hA * MODEL_DIM);
    const float4* sB = (const float4*)(g_fused + (size_t)hB * MODEL_DIM);
    float4* dA = (float4*)(out + (size_t)tA * MODEL_DIM);
    float4* dB = (float4*)(out + (size_t)tB * MODEL_DIM);

    float4 a0 = __ldg(sA + lane);
    float4 a1 = __ldg(sA + lane + 32);
    float4 a2 = __ldg(sA + lane + 64);
    float4 a3 = __ldg(sA + lane + 96);
    float4 b0 = __ldg(sB + lane);
    float4 b1 = __ldg(sB + lane + 32);
    float4 b2 = __ldg(sB + lane + 64);
    float4 b3 = __ldg(sB + lane + 96);

    __stcs(dA + lane,      a0);
    __stcs(dA + lane + 32, a1);
    __stcs(dA + lane + 64, a2);
    __stcs(dA + lane + 96, a3);
    __stcs(dB + lane,      b0);
    __stcs(dB + lane + 32, b1);
    __stcs(dB + lane + 64, b2);
    __stcs(dB + lane + 96, b3);
}

// ---------------------------------------------------------------------------
// Inputs (metadata order): token_ids(i32), embed_weight(f32), proj_weight(f32), scale(f32[1])
// ---------------------------------------------------------------------------
extern "C" void kernel_launch(void* const* d_in, const int* in_sizes, int n_in,
                              void* d_out, int out_size)
{
    const int*   tok   = (const int*)d_in[0];
    const float* E     = (const float*)d_in[1];
    const float* P     = (const float*)d_in[2];
    const float* scale = (const float*)d_in[3];
    float*       out   = (float*)d_out;

    dim3 gemm_grid(HASH_SIZE / GBM, MODEL_DIM / GBN);   // (80, 8)
    build_table_kernel<<<gemm_grid, 256>>>(E, P, scale);

    // 65536 tokens / 2 per warp = 8192 warps; 8 warps per block -> 4096 blocks
    gather_kernel<<<(NBATCH * SEQ) / 16, 256>>>(tok, out);
}